// round 6
// baseline (speedup 1.0000x reference)
#include <cuda_runtime.h>

// ---------------------------------------------------------------------------
// MogrifierRNN persistent kernel, round 5.
//   - contention-free flag barrier (padded per-block slots + go flag),
//     no atomics, no CCTL.IVALL
//   - NT=512 (4 warps/SMSP) for 2x latency hiding
//   - gates: h-tile prefetched into registers under the Wih GEMM
//   - smem-resident Whh slice; pitch-516 conflict-free LDS.128 A tiles
// ---------------------------------------------------------------------------

#define S_LEN 512
#define B_DIM 128
#define HID   512
#define K_RANK 256
#define NQP   2

#define GRID_BLOCKS 128
#define NT          512
#define APITCH      516          // floats per staged A row -> LDS.128 conflict-free

#define AS_FLOATS   (32 * APITCH)       // 16512
#define WH_FLOATS   (64 * HID)          // 32768
#define SMEM_BYTES  ((AS_FLOATS + WH_FLOATS) * 4)   // 197,120 B
#define BAR_STRIDE  32                  // 128B padding between arrive flags

// ------------------------- device scratch ----------------------------------
__device__ float g_Q[NQP * HID * HID];   // Q[i][m][n]
__device__ float g_R[NQP * HID * HID];   // R[i][n][m]
__device__ float g_xx[B_DIM * HID];
__device__ float g_h[2][B_DIM * HID];
__device__ float g_c[B_DIM * HID];
__device__ unsigned int g_arrive[GRID_BLOCKS * BAR_STRIDE];
__device__ unsigned int g_go;

__global__ void mg_init() {
    int i = (int)threadIdx.x;
    if (i < GRID_BLOCKS) g_arrive[i * BAR_STRIDE] = 0u;
    if (i == 0) g_go = 0u;
}

__device__ __forceinline__ float sigf(float v) {
    return 1.0f / (1.0f + __expf(-v));
}

__device__ __forceinline__ unsigned int ld_acq(const unsigned int* p) {
    unsigned int v;
    asm volatile("ld.acquire.gpu.global.u32 %0, [%1];"
                 : "=r"(v) : "l"(p) : "memory");
    return v;
}
__device__ __forceinline__ void st_rel(unsigned int* p, unsigned int v) {
    asm volatile("st.release.gpu.global.u32 [%0], %1;"
                 :: "l"(p), "r"(v) : "memory");
}

// Flag barrier: per-block padded arrive slots (parallel, contention-free),
// block 0 gathers with 128 threads, publishes go flag. release/acquire chain
// gives cross-SM visibility of the .cg activation stores; no L1 invalidation
// is needed because all cross-SM mutable data is read .cv / written .cg.
__device__ __forceinline__ void grid_barrier(unsigned int& epoch) {
    epoch++;
    __syncthreads();
    if (blockIdx.x == 0) {
        if (threadIdx.x == 0) st_rel(&g_arrive[0], epoch);
        if (threadIdx.x < GRID_BLOCKS) {
            while (ld_acq(&g_arrive[threadIdx.x * BAR_STRIDE]) < epoch) { }
        }
        __syncthreads();
        if (threadIdx.x == 0) st_rel(&g_go, epoch);
    } else {
        if (threadIdx.x == 0) {
            st_rel(&g_arrive[blockIdx.x * BAR_STRIDE], epoch);
            while (ld_acq(&g_go) < epoch) { }
        }
        __syncthreads();
    }
}

// Stage full A tile (32 rows x 512) into smem with L1-bypass reads.
__device__ __forceinline__ void stage_A(float* As, const float* A, int r0) {
#pragma unroll
    for (int i = 0; i < 8; i++) {
        int e   = i * NT + (int)threadIdx.x;   // 0..4095 float4 slots
        int row = e >> 7;
        int q   = e & 127;
        float4 v = __ldcv(reinterpret_cast<const float4*>(A + (r0 + row) * HID) + q);
        *reinterpret_cast<float4*>(As + row * APITCH + q * 4) = v;
    }
}

// Mogrifier phase: Out[b,j] = 2*sig(sum_k A[b,k] W[j,k]) * Mul[b,j]
// Tile 32 rows x 16 cols; warp = 1 col, lane = row.
__device__ __forceinline__ void mog_phase(float* As, const float* Aglob,
                                          const float* __restrict__ W,
                                          const float* Mul, float* Out,
                                          int r0, int j, int lane) {
    stage_A(As, Aglob, r0);
    const int b = r0 + lane;
    float m0 = __ldcv(Mul + b * HID + j);      // prefetch under the GEMM
    const float4* __restrict__ Wp = reinterpret_cast<const float4*>(W + j * HID);
    __syncthreads();

    const float4* Ar = reinterpret_cast<const float4*>(As + lane * APITCH);
    float acc0 = 0.f, acc1 = 0.f;
#pragma unroll 8
    for (int k4 = 0; k4 < HID / 4; k4++) {
        float4 a = Ar[k4];
        float4 w = Wp[k4];
        acc0 = fmaf(a.x, w.x, acc0); acc1 = fmaf(a.y, w.y, acc1);
        acc0 = fmaf(a.z, w.z, acc0); acc1 = fmaf(a.w, w.w, acc1);
    }
    __stcg(Out + b * HID + j, 2.0f * sigf(acc0 + acc1) * m0);
}

// Gates + LSTM pointwise. Warp = 1 n-col (4 gates); lane = row.
// src0: xx @ Wih^T (uniform LDG, L2); src1: h @ Whh^T (smem-resident).
// The h tile is prefetched into registers during src0 and stored to smem after.
__device__ __forceinline__ void gates_phase(float* As, const float* Wh,
                                            const float* __restrict__ Wih,
                                            const float* __restrict__ bih,
                                            const float* __restrict__ bhh,
                                            const float* hcur, float* hn,
                                            float* outp, float* tail,
                                            int r0, int j0, int j,
                                            int lane, int t) {
    stage_A(As, g_xx, r0);

    // prefetch h tile into registers (consumed after src0)
    float4 hreg[8];
#pragma unroll
    for (int i = 0; i < 8; i++) {
        int e   = i * NT + (int)threadIdx.x;
        int row = e >> 7;
        int q   = e & 127;
        hreg[i] = __ldcv(reinterpret_cast<const float4*>(hcur + (r0 + row) * HID) + q);
    }

    const int b = r0 + lane;
    float cprev = g_c[b * HID + j];
    float bsum0 = bih[j]        + bhh[j];
    float bsum1 = bih[512 + j]  + bhh[512 + j];
    float bsum2 = bih[1024 + j] + bhh[1024 + j];
    float bsum3 = bih[1536 + j] + bhh[1536 + j];

    float acc0 = 0.f, acc1 = 0.f, acc2 = 0.f, acc3 = 0.f;
    __syncthreads();

    const float4* Ar = reinterpret_cast<const float4*>(As + lane * APITCH);

    {   // ---- src0: xx @ Wih^T ----
        const float4* __restrict__ W0 = reinterpret_cast<const float4*>(Wih + (0 * HID + j) * HID);
        const float4* __restrict__ W1 = reinterpret_cast<const float4*>(Wih + (1 * HID + j) * HID);
        const float4* __restrict__ W2 = reinterpret_cast<const float4*>(Wih + (2 * HID + j) * HID);
        const float4* __restrict__ W3 = reinterpret_cast<const float4*>(Wih + (3 * HID + j) * HID);
#pragma unroll 4
        for (int k4 = 0; k4 < HID / 4; k4++) {
            float4 a = Ar[k4];
            float4 w;
            w = W0[k4];
            acc0 = fmaf(a.x, w.x, acc0); acc0 = fmaf(a.y, w.y, acc0);
            acc0 = fmaf(a.z, w.z, acc0); acc0 = fmaf(a.w, w.w, acc0);
            w = W1[k4];
            acc1 = fmaf(a.x, w.x, acc1); acc1 = fmaf(a.y, w.y, acc1);
            acc1 = fmaf(a.z, w.z, acc1); acc1 = fmaf(a.w, w.w, acc1);
            w = W2[k4];
            acc2 = fmaf(a.x, w.x, acc2); acc2 = fmaf(a.y, w.y, acc2);
            acc2 = fmaf(a.z, w.z, acc2); acc2 = fmaf(a.w, w.w, acc2);
            w = W3[k4];
            acc3 = fmaf(a.x, w.x, acc3); acc3 = fmaf(a.y, w.y, acc3);
            acc3 = fmaf(a.z, w.z, acc3); acc3 = fmaf(a.w, w.w, acc3);
        }
    }
    __syncthreads();
    // store prefetched h tile into smem
#pragma unroll
    for (int i = 0; i < 8; i++) {
        int e   = i * NT + (int)threadIdx.x;
        int row = e >> 7;
        int q   = e & 127;
        *reinterpret_cast<float4*>(As + row * APITCH + q * 4) = hreg[i];
    }
    __syncthreads();

    {   // ---- src1: h @ Whh^T (smem) ----
        const int jc = j - j0;
        const float4* S0 = reinterpret_cast<const float4*>(Wh + (0 * 16 + jc) * HID);
        const float4* S1 = reinterpret_cast<const float4*>(Wh + (1 * 16 + jc) * HID);
        const float4* S2 = reinterpret_cast<const float4*>(Wh + (2 * 16 + jc) * HID);
        const float4* S3 = reinterpret_cast<const float4*>(Wh + (3 * 16 + jc) * HID);
#pragma unroll 4
        for (int k4 = 0; k4 < HID / 4; k4++) {
            float4 a = Ar[k4];
            float4 w;
            w = S0[k4];
            acc0 = fmaf(a.x, w.x, acc0); acc0 = fmaf(a.y, w.y, acc0);
            acc0 = fmaf(a.z, w.z, acc0); acc0 = fmaf(a.w, w.w, acc0);
            w = S1[k4];
            acc1 = fmaf(a.x, w.x, acc1); acc1 = fmaf(a.y, w.y, acc1);
            acc1 = fmaf(a.z, w.z, acc1); acc1 = fmaf(a.w, w.w, acc1);
            w = S2[k4];
            acc2 = fmaf(a.x, w.x, acc2); acc2 = fmaf(a.y, w.y, acc2);
            acc2 = fmaf(a.z, w.z, acc2); acc2 = fmaf(a.w, w.w, acc2);
            w = S3[k4];
            acc3 = fmaf(a.x, w.x, acc3); acc3 = fmaf(a.y, w.y, acc3);
            acc3 = fmaf(a.z, w.z, acc3); acc3 = fmaf(a.w, w.w, acc3);
        }
    }

    // ---- LSTM pointwise ----
    float ig = acc0 + bsum0;
    float fg = acc1 + bsum1;
    float gg = acc2 + bsum2;
    float og = acc3 + bsum3;

    float c_new = sigf(fg) * cprev + sigf(ig) * tanhf(gg);
    float h_new = sigf(og) * tanhf(c_new);

    int idx = b * HID + j;
    g_c[idx] = c_new;
    __stcg(hn + idx, h_new);
    outp[idx] = h_new;
    if (t == S_LEN - 1) {
        tail[idx]               = h_new;
        tail[B_DIM * HID + idx] = c_new;
    }
}

// One-time precompute of Q = QL@QR, R = RL@RR; zero h0, c0.
__device__ void precompute(const float* QL, const float* QR,
                           const float* RL, const float* RR) {
    const int tid = (int)blockIdx.x * NT + (int)threadIdx.x;
    const int stride = GRID_BLOCKS * NT;
    for (int e = tid; e < NQP * HID * HID; e += stride) {
        int i = e >> 18;
        int rem = e & ((1 << 18) - 1);
        int m = rem >> 9, n = rem & 511;
        const float* L  = QL + i * HID * K_RANK + m * K_RANK;
        const float* Rp = QR + i * K_RANK * HID + n;
        float acc = 0.f;
#pragma unroll 8
        for (int k = 0; k < K_RANK; k++) acc = fmaf(L[k], Rp[k * HID], acc);
        g_Q[e] = acc;
    }
    for (int e = tid; e < NQP * HID * HID; e += stride) {
        int i = e >> 18;
        int rem = e & ((1 << 18) - 1);
        int n = rem >> 9, m = rem & 511;
        const float* L  = RL + i * HID * K_RANK + n * K_RANK;
        const float* Rp = RR + i * K_RANK * HID + m;
        float acc = 0.f;
#pragma unroll 8
        for (int k = 0; k < K_RANK; k++) acc = fmaf(L[k], Rp[k * HID], acc);
        g_R[e] = acc;
    }
    for (int e = tid; e < B_DIM * HID; e += stride) {
        g_h[0][e] = 0.f;
        g_c[e]    = 0.f;
    }
}

extern "C" __global__ void __launch_bounds__(NT, 1)
mogrifier_main(const float* __restrict__ x,
               const float* __restrict__ QL, const float* __restrict__ QR,
               const float* __restrict__ RL, const float* __restrict__ RR,
               const float* __restrict__ Wih, const float* __restrict__ Whh,
               const float* __restrict__ bih, const float* __restrict__ bhh,
               float* __restrict__ out) {
    extern __shared__ float smem[];
    float* As = smem;
    float* Wh = smem + AS_FLOATS;

    const int lane = threadIdx.x & 31, wp = (int)threadIdx.x >> 5;   // wp 0..15
    const int rt = blockIdx.x & 3, ct = (int)blockIdx.x >> 2;
    const int r0 = rt * 32, j0 = ct * 16;
    const int j = j0 + wp;
    unsigned int epoch = 0;

    precompute(QL, QR, RL, RR);

    // Stage this block's Whh slice (64 gate-rows x 512) into smem, once.
#pragma unroll
    for (int i = 0; i < 16; i++) {
        int e = i * NT + (int)threadIdx.x;   // 0..8191 float4
        int rowIdx = e >> 7, q = e & 127;
        int g = rowIdx >> 4, cc = rowIdx & 15;
        float4 v = *(reinterpret_cast<const float4*>(Whh + (g * HID + j0 + cc) * HID) + q);
        *reinterpret_cast<float4*>(Wh + rowIdx * HID + q * 4) = v;
    }

    grid_barrier(epoch);

    float* tail = out + (size_t)S_LEN * B_DIM * HID;

    for (int t = 0; t < S_LEN; t++) {
        float* hc = g_h[t & 1];
        float* hn = g_h[(t + 1) & 1];
        const float* xt = x + (size_t)t * B_DIM * HID;

        mog_phase(As, hc,   g_Q,             xt,   g_xx, r0, j, lane);
        grid_barrier(epoch);
        mog_phase(As, g_xx, g_R,             hc,   hc,   r0, j, lane);
        grid_barrier(epoch);
        mog_phase(As, hc,   g_Q + HID * HID, g_xx, g_xx, r0, j, lane);
        grid_barrier(epoch);
        mog_phase(As, g_xx, g_R + HID * HID, hc,   hc,   r0, j, lane);
        grid_barrier(epoch);
        gates_phase(As, Wh, Wih, bih, bhh, hc, hn,
                    out + (size_t)t * B_DIM * HID, tail,
                    r0, j0, j, lane, t);
        grid_barrier(epoch);
    }
}

extern "C" void kernel_launch(void* const* d_in, const int* in_sizes, int n_in,
                              void* d_out, int out_size) {
    const float* x   = (const float*)d_in[0];
    const float* QL  = (const float*)d_in[1];
    const float* QR  = (const float*)d_in[2];
    const float* RL  = (const float*)d_in[3];
    const float* RR  = (const float*)d_in[4];
    const float* Wih = (const float*)d_in[5];
    const float* Whh = (const float*)d_in[6];
    const float* bih = (const float*)d_in[7];
    const float* bhh = (const float*)d_in[8];
    (void)in_sizes; (void)n_in; (void)out_size;

    cudaFuncSetAttribute(mogrifier_main,
                         cudaFuncAttributeMaxDynamicSharedMemorySize, SMEM_BYTES);

    mg_init<<<1, 128>>>();
    mogrifier_main<<<GRID_BLOCKS, NT, SMEM_BYTES>>>(x, QL, QR, RL, RR,
                                                    Wih, Whh, bih, bhh,
                                                    (float*)d_out);
}

// round 7
// speedup vs baseline: 1.1514x; 1.1514x over previous
#include <cuda_runtime.h>

// ---------------------------------------------------------------------------
// MogrifierRNN persistent kernel, round 6.
//   - R4-proven tiling: NT=256, 32x16 tile, 2 cols/thread (best L1/fma balance)
//   - R5 contention-free flag barrier (no atomics, no CCTL.IVALL)
//   - fma.rn.f32x2 over k-pairs (packed fp32 FMA, zero packing overhead)
//   - Whh slice smem-resident; pitch-516 conflict-free LDS.128 A tiles
// ---------------------------------------------------------------------------

#define S_LEN 512
#define B_DIM 128
#define HID   512
#define K_RANK 256
#define NQP   2

#define GRID_BLOCKS 128
#define NT          256
#define APITCH      516

#define AS_FLOATS   (32 * APITCH)
#define WH_FLOATS   (64 * HID)
#define SMEM_BYTES  ((AS_FLOATS + WH_FLOATS) * 4)   // 197,120 B
#define BAR_STRIDE  32

typedef unsigned long long u64;

// ------------------------- device scratch ----------------------------------
__device__ float g_Q[NQP * HID * HID];   // Q[i][m][n]
__device__ float g_R[NQP * HID * HID];   // R[i][n][m]
__device__ float g_xx[B_DIM * HID];
__device__ float g_h[2][B_DIM * HID];
__device__ float g_c[B_DIM * HID];
__device__ unsigned int g_arrive[GRID_BLOCKS * BAR_STRIDE];
__device__ unsigned int g_go;

__global__ void mg_init() {
    int i = (int)threadIdx.x;
    if (i < GRID_BLOCKS) g_arrive[i * BAR_STRIDE] = 0u;
    if (i == 0) g_go = 0u;
}

__device__ __forceinline__ float sigf(float v) {
    return 1.0f / (1.0f + __expf(-v));
}

// ---- packed fp32x2 FMA (Blackwell) ----------------------------------------
union F4 { float4 f; ulonglong2 d; };   // d.x = pack(f.x,f.y), d.y = pack(f.z,f.w)

__device__ __forceinline__ void ffma2(u64& acc, u64 a, u64 b) {
    asm("fma.rn.f32x2 %0, %1, %2, %0;" : "+l"(acc) : "l"(a), "l"(b));
}
__device__ __forceinline__ float pairsum(u64 p) {
    return __uint_as_float((unsigned)p) + __uint_as_float((unsigned)(p >> 32));
}

// ---- barrier primitives ----------------------------------------------------
__device__ __forceinline__ unsigned int ld_acq(const unsigned int* p) {
    unsigned int v;
    asm volatile("ld.acquire.gpu.global.u32 %0, [%1];"
                 : "=r"(v) : "l"(p) : "memory");
    return v;
}
__device__ __forceinline__ void st_rel(unsigned int* p, unsigned int v) {
    asm volatile("st.release.gpu.global.u32 [%0], %1;"
                 :: "l"(p), "r"(v) : "memory");
}

// Flag barrier: per-block padded arrive slots, block 0 gathers with 128
// threads, publishes go. release/acquire chain orders the .cg activation
// stores; consumers read .cv, so no L1 invalidation is ever needed.
__device__ __forceinline__ void grid_barrier(unsigned int& epoch) {
    epoch++;
    __syncthreads();
    if (blockIdx.x == 0) {
        if (threadIdx.x == 0) st_rel(&g_arrive[0], epoch);
        if (threadIdx.x < GRID_BLOCKS) {
            while (ld_acq(&g_arrive[threadIdx.x * BAR_STRIDE]) < epoch) { }
        }
        __syncthreads();
        if (threadIdx.x == 0) st_rel(&g_go, epoch);
    } else {
        if (threadIdx.x == 0) {
            st_rel(&g_arrive[blockIdx.x * BAR_STRIDE], epoch);
            while (ld_acq(&g_go) < epoch) { }
        }
        __syncthreads();
    }
}

// Stage full A tile (32 rows x 512) into smem with L1-bypass reads.
__device__ __forceinline__ void stage_A(float* As, const float* A, int r0) {
#pragma unroll
    for (int i = 0; i < 16; i++) {
        int e   = i * NT + (int)threadIdx.x;   // 0..4095 float4 slots
        int row = e >> 7;
        int q   = e & 127;
        float4 v = __ldcv(reinterpret_cast<const float4*>(A + (r0 + row) * HID) + q);
        *reinterpret_cast<float4*>(As + row * APITCH + q * 4) = v;
    }
}

// Mogrifier phase: Out[b,j] = 2*sig(sum_k A[b,k] W[j,k]) * Mul[b,j]
// Tile 32 rows x 16 cols; thread = 1 row (lane) x 2 cols.
__device__ __forceinline__ void mog_phase(float* As, const float* Aglob,
                                          const float* __restrict__ W,
                                          const float* Mul, float* Out,
                                          int r0, int jA, int jB, int lane) {
    stage_A(As, Aglob, r0);
    const int b = r0 + lane;
    float m0 = __ldcv(Mul + b * HID + jA);      // prefetch under the GEMM
    float m1 = __ldcv(Mul + b * HID + jB);
    __syncthreads();

    const float4* __restrict__ WA = reinterpret_cast<const float4*>(W + jA * HID);
    const float4* __restrict__ WB = reinterpret_cast<const float4*>(W + jB * HID);
    const float4* Ar = reinterpret_cast<const float4*>(As + lane * APITCH);

    u64 acc0 = 0ull, acc1 = 0ull;
#pragma unroll 8
    for (int k4 = 0; k4 < HID / 4; k4++) {
        F4 a, w0, w1;
        a.f  = Ar[k4];
        w0.f = WA[k4];
        w1.f = WB[k4];
        ffma2(acc0, a.d.x, w0.d.x); ffma2(acc0, a.d.y, w0.d.y);
        ffma2(acc1, a.d.x, w1.d.x); ffma2(acc1, a.d.y, w1.d.y);
    }
    __stcg(Out + b * HID + jA, 2.0f * sigf(pairsum(acc0)) * m0);
    __stcg(Out + b * HID + jB, 2.0f * sigf(pairsum(acc1)) * m1);
}

// Gates + LSTM pointwise. Thread = 1 row x 2 n-cols x 4 gates (8 acc pairs).
// src0: xx @ Wih^T (uniform LDG, L2); src1: h @ Whh^T (smem-resident slice).
__device__ __forceinline__ void gates_phase(float* As, const float* Wh,
                                            const float* __restrict__ Wih,
                                            const float* __restrict__ bih,
                                            const float* __restrict__ bhh,
                                            const float* hcur, float* hn,
                                            float* outp, float* tail,
                                            int r0, int j0, int jA, int jB,
                                            int lane, int t) {
    stage_A(As, g_xx, r0);
    const int b = r0 + lane;
    float cA = g_c[b * HID + jA];
    float cB = g_c[b * HID + jB];
    float bA0 = bih[jA]        + bhh[jA];
    float bA1 = bih[512 + jA]  + bhh[512 + jA];
    float bA2 = bih[1024 + jA] + bhh[1024 + jA];
    float bA3 = bih[1536 + jA] + bhh[1536 + jA];
    float bB0 = bih[jB]        + bhh[jB];
    float bB1 = bih[512 + jB]  + bhh[512 + jB];
    float bB2 = bih[1024 + jB] + bhh[1024 + jB];
    float bB3 = bih[1536 + jB] + bhh[1536 + jB];

    u64 acc[8];
#pragma unroll
    for (int s = 0; s < 8; s++) acc[s] = 0ull;
    __syncthreads();

    const float4* Ar = reinterpret_cast<const float4*>(As + lane * APITCH);

    {   // ---- src0: xx @ Wih^T ----
        const float4* __restrict__ W0A = reinterpret_cast<const float4*>(Wih + (0 * HID + jA) * HID);
        const float4* __restrict__ W1A = reinterpret_cast<const float4*>(Wih + (1 * HID + jA) * HID);
        const float4* __restrict__ W2A = reinterpret_cast<const float4*>(Wih + (2 * HID + jA) * HID);
        const float4* __restrict__ W3A = reinterpret_cast<const float4*>(Wih + (3 * HID + jA) * HID);
        const float4* __restrict__ W0B = reinterpret_cast<const float4*>(Wih + (0 * HID + jB) * HID);
        const float4* __restrict__ W1B = reinterpret_cast<const float4*>(Wih + (1 * HID + jB) * HID);
        const float4* __restrict__ W2B = reinterpret_cast<const float4*>(Wih + (2 * HID + jB) * HID);
        const float4* __restrict__ W3B = reinterpret_cast<const float4*>(Wih + (3 * HID + jB) * HID);
#pragma unroll 4
        for (int k4 = 0; k4 < HID / 4; k4++) {
            F4 a; a.f = Ar[k4];
            F4 w;
            w.f = W0A[k4]; ffma2(acc[0], a.d.x, w.d.x); ffma2(acc[0], a.d.y, w.d.y);
            w.f = W1A[k4]; ffma2(acc[1], a.d.x, w.d.x); ffma2(acc[1], a.d.y, w.d.y);
            w.f = W2A[k4]; ffma2(acc[2], a.d.x, w.d.x); ffma2(acc[2], a.d.y, w.d.y);
            w.f = W3A[k4]; ffma2(acc[3], a.d.x, w.d.x); ffma2(acc[3], a.d.y, w.d.y);
            w.f = W0B[k4]; ffma2(acc[4], a.d.x, w.d.x); ffma2(acc[4], a.d.y, w.d.y);
            w.f = W1B[k4]; ffma2(acc[5], a.d.x, w.d.x); ffma2(acc[5], a.d.y, w.d.y);
            w.f = W2B[k4]; ffma2(acc[6], a.d.x, w.d.x); ffma2(acc[6], a.d.y, w.d.y);
            w.f = W3B[k4]; ffma2(acc[7], a.d.x, w.d.x); ffma2(acc[7], a.d.y, w.d.y);
        }
    }
    __syncthreads();
    stage_A(As, hcur, r0);
    __syncthreads();

    {   // ---- src1: h @ Whh^T (smem, warp-uniform broadcast reads) ----
        const int jcA = jA - j0, jcB = jB - j0;
        const float4* S0A = reinterpret_cast<const float4*>(Wh + (0 * 16 + jcA) * HID);
        const float4* S1A = reinterpret_cast<const float4*>(Wh + (1 * 16 + jcA) * HID);
        const float4* S2A = reinterpret_cast<const float4*>(Wh + (2 * 16 + jcA) * HID);
        const float4* S3A = reinterpret_cast<const float4*>(Wh + (3 * 16 + jcA) * HID);
        const float4* S0B = reinterpret_cast<const float4*>(Wh + (0 * 16 + jcB) * HID);
        const float4* S1B = reinterpret_cast<const float4*>(Wh + (1 * 16 + jcB) * HID);
        const float4* S2B = reinterpret_cast<const float4*>(Wh + (2 * 16 + jcB) * HID);
        const float4* S3B = reinterpret_cast<const float4*>(Wh + (3 * 16 + jcB) * HID);
#pragma unroll 4
        for (int k4 = 0; k4 < HID / 4; k4++) {
            F4 a; a.f = Ar[k4];
            F4 w;
            w.f = S0A[k4]; ffma2(acc[0], a.d.x, w.d.x); ffma2(acc[0], a.d.y, w.d.y);
            w.f = S1A[k4]; ffma2(acc[1], a.d.x, w.d.x); ffma2(acc[1], a.d.y, w.d.y);
            w.f = S2A[k4]; ffma2(acc[2], a.d.x, w.d.x); ffma2(acc[2], a.d.y, w.d.y);
            w.f = S3A[k4]; ffma2(acc[3], a.d.x, w.d.x); ffma2(acc[3], a.d.y, w.d.y);
            w.f = S0B[k4]; ffma2(acc[4], a.d.x, w.d.x); ffma2(acc[4], a.d.y, w.d.y);
            w.f = S1B[k4]; ffma2(acc[5], a.d.x, w.d.x); ffma2(acc[5], a.d.y, w.d.y);
            w.f = S2B[k4]; ffma2(acc[6], a.d.x, w.d.x); ffma2(acc[6], a.d.y, w.d.y);
            w.f = S3B[k4]; ffma2(acc[7], a.d.x, w.d.x); ffma2(acc[7], a.d.y, w.d.y);
        }
    }

    // ---- LSTM pointwise ----
    float igA = pairsum(acc[0]) + bA0;
    float fgA = pairsum(acc[1]) + bA1;
    float ggA = pairsum(acc[2]) + bA2;
    float ogA = pairsum(acc[3]) + bA3;
    float igB = pairsum(acc[4]) + bB0;
    float fgB = pairsum(acc[5]) + bB1;
    float ggB = pairsum(acc[6]) + bB2;
    float ogB = pairsum(acc[7]) + bB3;

    float cnA = sigf(fgA) * cA + sigf(igA) * tanhf(ggA);
    float hA  = sigf(ogA) * tanhf(cnA);
    float cnB = sigf(fgB) * cB + sigf(igB) * tanhf(ggB);
    float hB  = sigf(ogB) * tanhf(cnB);

    int idxA = b * HID + jA, idxB = b * HID + jB;
    g_c[idxA] = cnA;  g_c[idxB] = cnB;
    __stcg(hn + idxA, hA);  __stcg(hn + idxB, hB);
    outp[idxA] = hA;  outp[idxB] = hB;
    if (t == S_LEN - 1) {
        tail[idxA] = hA;  tail[B_DIM * HID + idxA] = cnA;
        tail[idxB] = hB;  tail[B_DIM * HID + idxB] = cnB;
    }
}

// One-time precompute of Q = QL@QR, R = RL@RR; zero h0, c0.
__device__ void precompute(const float* QL, const float* QR,
                           const float* RL, const float* RR) {
    const int tid = (int)blockIdx.x * NT + (int)threadIdx.x;
    const int stride = GRID_BLOCKS * NT;
    for (int e = tid; e < NQP * HID * HID; e += stride) {
        int i = e >> 18;
        int rem = e & ((1 << 18) - 1);
        int m = rem >> 9, n = rem & 511;
        const float* L  = QL + i * HID * K_RANK + m * K_RANK;
        const float* Rp = QR + i * K_RANK * HID + n;
        float acc = 0.f;
#pragma unroll 8
        for (int k = 0; k < K_RANK; k++) acc = fmaf(L[k], Rp[k * HID], acc);
        g_Q[e] = acc;
    }
    for (int e = tid; e < NQP * HID * HID; e += stride) {
        int i = e >> 18;
        int rem = e & ((1 << 18) - 1);
        int n = rem >> 9, m = rem & 511;
        const float* L  = RL + i * HID * K_RANK + n * K_RANK;
        const float* Rp = RR + i * K_RANK * HID + m;
        float acc = 0.f;
#pragma unroll 8
        for (int k = 0; k < K_RANK; k++) acc = fmaf(L[k], Rp[k * HID], acc);
        g_R[e] = acc;
    }
    for (int e = tid; e < B_DIM * HID; e += stride) {
        g_h[0][e] = 0.f;
        g_c[e]    = 0.f;
    }
}

extern "C" __global__ void __launch_bounds__(NT, 1)
mogrifier_main(const float* __restrict__ x,
               const float* __restrict__ QL, const float* __restrict__ QR,
               const float* __restrict__ RL, const float* __restrict__ RR,
               const float* __restrict__ Wih, const float* __restrict__ Whh,
               const float* __restrict__ bih, const float* __restrict__ bhh,
               float* __restrict__ out) {
    extern __shared__ float smem[];
    float* As = smem;
    float* Wh = smem + AS_FLOATS;

    const int lane = threadIdx.x & 31, wp = (int)threadIdx.x >> 5;   // wp 0..7
    const int rt = blockIdx.x & 3, ct = (int)blockIdx.x >> 2;
    const int r0 = rt * 32, j0 = ct * 16;
    const int jA = j0 + 2 * wp, jB = jA + 1;
    unsigned int epoch = 0;

    precompute(QL, QR, RL, RR);

    // Stage this block's Whh slice (64 gate-rows x 512) into smem, once.
#pragma unroll
    for (int i = 0; i < 32; i++) {
        int e = i * NT + (int)threadIdx.x;   // 0..8191 float4
        int rowIdx = e >> 7, q = e & 127;
        int g = rowIdx >> 4, cc = rowIdx & 15;
        float4 v = *(reinterpret_cast<const float4*>(Whh + (g * HID + j0 + cc) * HID) + q);
        *reinterpret_cast<float4*>(Wh + rowIdx * HID + q * 4) = v;
    }

    grid_barrier(epoch);

    float* tail = out + (size_t)S_LEN * B_DIM * HID;

    for (int t = 0; t < S_LEN; t++) {
        float* hc = g_h[t & 1];
        float* hn = g_h[(t + 1) & 1];
        const float* xt = x + (size_t)t * B_DIM * HID;

        mog_phase(As, hc,   g_Q,             xt,   g_xx, r0, jA, jB, lane);
        grid_barrier(epoch);
        mog_phase(As, g_xx, g_R,             hc,   hc,   r0, jA, jB, lane);
        grid_barrier(epoch);
        mog_phase(As, hc,   g_Q + HID * HID, g_xx, g_xx, r0, jA, jB, lane);
        grid_barrier(epoch);
        mog_phase(As, g_xx, g_R + HID * HID, hc,   hc,   r0, jA, jB, lane);
        grid_barrier(epoch);
        gates_phase(As, Wh, Wih, bih, bhh, hc, hn,
                    out + (size_t)t * B_DIM * HID, tail,
                    r0, j0, jA, jB, lane, t);
        grid_barrier(epoch);
    }
}

extern "C" void kernel_launch(void* const* d_in, const int* in_sizes, int n_in,
                              void* d_out, int out_size) {
    const float* x   = (const float*)d_in[0];
    const float* QL  = (const float*)d_in[1];
    const float* QR  = (const float*)d_in[2];
    const float* RL  = (const float*)d_in[3];
    const float* RR  = (const float*)d_in[4];
    const float* Wih = (const float*)d_in[5];
    const float* Whh = (const float*)d_in[6];
    const float* bih = (const float*)d_in[7];
    const float* bhh = (const float*)d_in[8];
    (void)in_sizes; (void)n_in; (void)out_size;

    cudaFuncSetAttribute(mogrifier_main,
                         cudaFuncAttributeMaxDynamicSharedMemorySize, SMEM_BYTES);

    mg_init<<<1, 128>>>();
    mogrifier_main<<<GRID_BLOCKS, NT, SMEM_BYTES>>>(x, QL, QR, RL, RR,
                                                    Wih, Whh, bih, bhh,
                                                    (float*)d_out);
}